// round 1
// baseline (speedup 1.0000x reference)
#include <cuda_runtime.h>
#include <cstdint>

#define NB 32
#define NT 1024
#define ND 512
#define NU 64

// Scratch (device globals: no allocation allowed in kernel_launch)
__device__ float g_C[2ull * NB * ND * 128]; // x_s^T @ [w2|w3], 16.8 MB
__device__ float g_M[2ull * NB * ND * NU];  // per-branch M matrices, 8.4 MB
__device__ float g_E[2 * NB * NT];          // raw scores e
__device__ float g_W[2 * NB * NT];          // softmax weights ww

// ---- packed fp32x2 helpers (sm_103a FFMA2) ----
__device__ __forceinline__ void ffma2(unsigned long long& acc, unsigned long long a,
                                      unsigned long long b) {
    asm("fma.rn.f32x2 %0, %1, %2, %0;" : "+l"(acc) : "l"(a), "l"(b));
}
__device__ __forceinline__ unsigned long long pack2(float lo, float hi) {
    unsigned long long r;
    asm("mov.b64 %0, {%1, %2};" : "=l"(r) : "f"(lo), "f"(hi));
    return r;
}
__device__ __forceinline__ float2 unpack2(unsigned long long v) {
    float2 r;
    asm("mov.b64 {%0, %1}, %2;" : "=f"(r.x), "=f"(r.y) : "l"(v));
    return r;
}

// ============================================================
// K1: C[s][b] = X_s[b]^T @ [w2 | w3]   (D=512 x 128, K=T=1024)
// block tile 64(d) x 128(u), 256 threads, thread tile 8d x 4u
// accumulators packed along d (a-pairs direct from smem).
// ============================================================
__global__ void __launch_bounds__(256) k1_xtw(const float* __restrict__ x1,
                                              const float* __restrict__ x2,
                                              const float* __restrict__ w2,
                                              const float* __restrict__ w3) {
    __shared__ float Xs[32][64];
    __shared__ float Ws[32][128];
    const int dt = blockIdx.x;  // 0..7 (d tile)
    const int b = blockIdx.y;
    const int s = blockIdx.z;
    const float* __restrict__ X = s ? x2 : x1;
    const int tid = threadIdx.x;
    const int ux = tid & 31;  // u group (4 u's)
    const int dy = tid >> 5;  // d group (8 d's)
    const int d0 = dt * 64;

    unsigned long long acc[4][4];
#pragma unroll
    for (int i = 0; i < 4; i++)
#pragma unroll
        for (int j = 0; j < 4; j++) acc[i][j] = 0ull;

    for (int k0 = 0; k0 < NT; k0 += 32) {
        // X tile: 32 t-rows x 64 d (contiguous along d)
#pragma unroll
        for (int i = 0; i < 2; i++) {
            int f = tid + i * 256;
            int r = f >> 4, c = (f & 15) << 2;
            *(float4*)&Xs[r][c] =
                *(const float4*)(X + ((size_t)b * NT + k0 + r) * ND + d0 + c);
        }
        // W tile: 32 t-rows x 128 u ([w2 | w3])
#pragma unroll
        for (int i = 0; i < 4; i++) {
            int f = tid + i * 256;
            int r = f >> 5, c = f & 31;
            const float* src = (c < 16) ? (w2 + (size_t)(k0 + r) * NU + (c << 2))
                                        : (w3 + (size_t)(k0 + r) * NU + ((c - 16) << 2));
            *(float4*)&Ws[r][c << 2] = *(const float4*)src;
        }
        __syncthreads();
#pragma unroll
        for (int k = 0; k < 32; k++) {
            const ulonglong2 a01 = *(const ulonglong2*)&Xs[k][dy * 8];
            const ulonglong2 a23 = *(const ulonglong2*)&Xs[k][dy * 8 + 4];
            const float4 bv = *(const float4*)&Ws[k][ux * 4];
            unsigned long long av[4] = {a01.x, a01.y, a23.x, a23.y};
            unsigned long long bd[4] = {pack2(bv.x, bv.x), pack2(bv.y, bv.y),
                                        pack2(bv.z, bv.z), pack2(bv.w, bv.w)};
#pragma unroll
            for (int i = 0; i < 4; i++)
#pragma unroll
                for (int j = 0; j < 4; j++) ffma2(acc[i][j], av[i], bd[j]);
        }
        __syncthreads();
    }
    float* Cb = g_C + (size_t)(s * NB + b) * ND * 128;
#pragma unroll
    for (int i = 0; i < 4; i++) {
        int d = d0 + dy * 8 + i * 2;
#pragma unroll
        for (int j = 0; j < 4; j++) {
            float2 v = unpack2(acc[i][j]);
            int u = ux * 4 + j;
            Cb[(size_t)d * 128 + u] = v.x;
            Cb[(size_t)(d + 1) * 128 + u] = v.y;
        }
    }
}

// ============================================================
// K_prep: M[s][b][d][u] = C[1-s][b][d][u] + C[s][b][d][64+u] + w1[d][u]
// ============================================================
__global__ void __launch_bounds__(256) k_prep(const float* __restrict__ w1) {
    int i = blockIdx.x * 256 + threadIdx.x;  // over 2*NB*ND*NU = 2097152
    int u = i & 63;
    int d = (i >> 6) & (ND - 1);
    int sb = i >> 15;  // s*32+b
    int s = sb >> 5, b = sb & 31;
    float v = g_C[(((size_t)((1 - s) * NB + b) * ND + d) << 7) + u] +
              g_C[(((size_t)(s * NB + b) * ND + d) << 7) + 64 + u] + w1[d * NU + u];
    g_M[i] = v;
}

// ============================================================
// K2: e[s][b][t] = 10 * sum_u tanh( (X_s[b] @ M_s[b])[t,u] ) * we[u]
// block tile 128(t) x 64(u), K=D=512, 256 threads, thread tile 4t x 8u,
// accumulators packed along u (b-pairs direct from smem).
// ============================================================
__global__ void __launch_bounds__(256) k2_he(const float* __restrict__ x1,
                                             const float* __restrict__ x2,
                                             const float* __restrict__ we) {
    __shared__ float Xs[128][36];  // [t][k], padded row
    __shared__ float Ms[32][64];   // [k][u]
    __shared__ float wes[64];
    __shared__ float red[128][8];
    const int tt = blockIdx.x;  // 0..7 (t tile)
    const int b = blockIdx.y;
    const int s = blockIdx.z;
    const float* __restrict__ X = s ? x2 : x1;
    const int tid = threadIdx.x;
    const int ug = tid & 7;   // u group (8 u's)
    const int tg = tid >> 3;  // t group (4 t's)
    const int t0 = tt * 128;
    const int sb = s * NB + b;

    if (tid < 64) wes[tid] = we[tid];

    unsigned long long acc[4][4];
#pragma unroll
    for (int i = 0; i < 4; i++)
#pragma unroll
        for (int j = 0; j < 4; j++) acc[i][j] = 0ull;

    const float* __restrict__ Mb = g_M + (size_t)sb * ND * NU;

    for (int k0 = 0; k0 < ND; k0 += 32) {
#pragma unroll
        for (int i = 0; i < 4; i++) {
            int f = tid + i * 256;
            int t = f >> 3, kc = (f & 7) << 2;
            *(float4*)&Xs[t][kc] =
                *(const float4*)(X + ((size_t)b * NT + t0 + t) * ND + k0 + kc);
        }
#pragma unroll
        for (int i = 0; i < 2; i++) {
            int f = tid + i * 256;
            int r = f >> 4, c = (f & 15) << 2;
            *(float4*)&Ms[r][c] = *(const float4*)(Mb + (size_t)(k0 + r) * NU + c);
        }
        __syncthreads();
#pragma unroll
        for (int k = 0; k < 32; k++) {
            const ulonglong2 b01 = *(const ulonglong2*)&Ms[k][ug * 8];
            const ulonglong2 b23 = *(const ulonglong2*)&Ms[k][ug * 8 + 4];
            unsigned long long bv[4] = {b01.x, b01.y, b23.x, b23.y};
            unsigned long long ad[4];
#pragma unroll
            for (int i = 0; i < 4; i++) {
                float a = Xs[tg * 4 + i][k];
                ad[i] = pack2(a, a);
            }
#pragma unroll
            for (int i = 0; i < 4; i++)
#pragma unroll
                for (int j = 0; j < 4; j++) ffma2(acc[i][j], ad[i], bv[j]);
        }
        __syncthreads();
    }
    // epilogue: partial e per thread over its 8 u's, then reduce across ug
#pragma unroll
    for (int i = 0; i < 4; i++) {
        float p = 0.f;
#pragma unroll
        for (int j = 0; j < 4; j++) {
            float2 h = unpack2(acc[i][j]);
            int u = ug * 8 + j * 2;
            p += tanhf(h.x) * wes[u] + tanhf(h.y) * wes[u + 1];
        }
        red[tg * 4 + i][ug] = p;
    }
    __syncthreads();
    if (tid < 128) {
        float e = 0.f;
#pragma unroll
        for (int q = 0; q < 8; q++) e += red[tid][q];
        g_E[sb * NT + t0 + tid] = 10.0f * e;
    }
}

// ============================================================
// K3: softmax over T per (s,b):  ww = exp(e) / (sum(exp(e)) + 1e-7)
// (unstabilized, matching the reference exactly)
// ============================================================
__global__ void __launch_bounds__(256) k3_softmax() {
    const int sb = blockIdx.x;
    const int tid = threadIdx.x;
    __shared__ float ssum[8];
    float a[4];
    float lsum = 0.f;
#pragma unroll
    for (int i = 0; i < 4; i++) {
        a[i] = expf(g_E[sb * NT + tid + i * 256]);
        lsum += a[i];
    }
#pragma unroll
    for (int o = 16; o; o >>= 1) lsum += __shfl_xor_sync(0xffffffffu, lsum, o);
    if ((tid & 31) == 0) ssum[tid >> 5] = lsum;
    __syncthreads();
    if (tid == 0) {
        float sT = 0.f;
#pragma unroll
        for (int q = 0; q < 8; q++) sT += ssum[q];
        ssum[0] = 1.0f / (sT + 1e-7f);
    }
    __syncthreads();
    float inv = ssum[0];
#pragma unroll
    for (int i = 0; i < 4; i++) g_W[sb * NT + tid + i * 256] = a[i] * inv;
}

// ============================================================
// K4: out[s][b][t][d] = X_s[b][t][d] * ww[s][b][t]   (float4 streaming)
// ============================================================
__global__ void __launch_bounds__(256) k4_scale(const float* __restrict__ x1,
                                                const float* __restrict__ x2,
                                                float* __restrict__ out) {
    size_t f = (size_t)blockIdx.x * 256 + threadIdx.x;  // float4 index
    int d4 = (int)(f & 127);
    int t = (int)((f >> 7) & 1023);
    int sb = (int)(f >> 17);  // 0..63
    const float* __restrict__ X = (sb >= NB) ? x2 : x1;
    int b = sb & 31;
    float w = g_W[sb * NT + t];
    float4 v = *(const float4*)(X + ((size_t)b * NT + t) * ND + (d4 << 2));
    v.x *= w;
    v.y *= w;
    v.z *= w;
    v.w *= w;
    ((float4*)out)[f] = v;
}

extern "C" void kernel_launch(void* const* d_in, const int* in_sizes, int n_in,
                              void* d_out, int out_size) {
    const float* x1 = (const float*)d_in[0];
    const float* x2 = (const float*)d_in[1];
    const float* w1 = (const float*)d_in[2];
    const float* w2 = (const float*)d_in[3];
    const float* w3 = (const float*)d_in[4];
    const float* we = (const float*)d_in[5];
    float* out = (float*)d_out;

    dim3 g1(ND / 64, NB, 2);
    k1_xtw<<<g1, 256>>>(x1, x2, w2, w3);

    k_prep<<<(2 * NB * ND * NU) / 256, 256>>>(w1);

    dim3 g2(NT / 128, NB, 2);
    k2_he<<<g2, 256>>>(x1, x2, we);

    k3_softmax<<<2 * NB, 256>>>();

    k4_scale<<<(2u * NB * NT * (ND / 4)) / 256, 256>>>(x1, x2, out);
}